// round 2
// baseline (speedup 1.0000x reference)
#include <cuda_runtime.h>
#include <cstdint>

// IDWT_2D: x [B=4, 4*C=256, H=256, W=256] f32, filters [4,2,2] f32
// s[b,g,h,w] = sum_n x[b, n*64+g, h, w]
// y[b, g*4+j, 2h+a, 2w+c] = s[b,g,h,w] * f[j,a,c]
// Output: [4, 256, 512, 512] f32

static constexpr int B = 4;
static constexpr int C = 64;    // groups
static constexpr int H = 256;
static constexpr int W = 256;
static constexpr int W4 = W / 4;           // float4 columns per row = 64
static constexpr int IN_CH_STRIDE = H * W; // 65536
static constexpr int OUT_W = 2 * W;        // 512
static constexpr int OUT_CH_STRIDE = (2 * H) * OUT_W; // 512*512

__global__ __launch_bounds__(256) void idwt2d_kernel(
    const float* __restrict__ x,
    const float* __restrict__ filters,
    float* __restrict__ out)
{
    // one thread = one (b, g, h, 4-wide w vector)
    unsigned t = blockIdx.x * 256u + threadIdx.x;
    int wv = t & (W4 - 1);          // 0..63
    int h  = (t >> 6) & (H - 1);    // 0..255
    int g  = (t >> 14) & (C - 1);   // 0..63
    int b  = t >> 20;               // 0..3

    // ---- gather + sum the 4 wavelet sub-band input channels ----
    // input channel for sub-band n, group g: n*C + g
    // streaming loads: data is read exactly once, evict-first
    const float4* xin = reinterpret_cast<const float4*>(
        x + (((size_t)(b * 4 * C + g) * H + h) * W)) + wv;
    float4 v0 = __ldcs(xin + 0 * (C * IN_CH_STRIDE / 4));
    float4 v1 = __ldcs(xin + 1 * (C * IN_CH_STRIDE / 4));
    float4 v2 = __ldcs(xin + 2 * (C * IN_CH_STRIDE / 4));
    float4 v3 = __ldcs(xin + 3 * (C * IN_CH_STRIDE / 4));
    float4 s;
    s.x = (v0.x + v1.x) + (v2.x + v3.x);
    s.y = (v0.y + v1.y) + (v2.y + v3.y);
    s.z = (v0.z + v1.z) + (v2.z + v3.z);
    s.w = (v0.w + v1.w) + (v2.w + v3.w);

    // ---- filters: [4,2,2], one float4 per j: {a0c0, a0c1, a1c0, a1c1} ----
    const float4* f4 = reinterpret_cast<const float4*>(filters);

    // output base for (b, g, j=0, row 2h, col 2*wv*4)
    float* obase = out + ((size_t)(b * 4 * C + g * 4) * (2 * H) + 2 * h) * OUT_W
                       + 8 * wv;

    #pragma unroll
    for (int j = 0; j < 4; ++j) {
        float4 F = __ldg(f4 + j);
        float* orow = obase + (size_t)j * OUT_CH_STRIDE;
        // a = 0 row — streaming stores: written once, never re-read
        float4 lo, hi;
        lo.x = s.x * F.x; lo.y = s.x * F.y; lo.z = s.y * F.x; lo.w = s.y * F.y;
        hi.x = s.z * F.x; hi.y = s.z * F.y; hi.z = s.w * F.x; hi.w = s.w * F.y;
        __stcs(reinterpret_cast<float4*>(orow) + 0, lo);
        __stcs(reinterpret_cast<float4*>(orow) + 1, hi);
        // a = 1 row
        lo.x = s.x * F.z; lo.y = s.x * F.w; lo.z = s.y * F.z; lo.w = s.y * F.w;
        hi.x = s.z * F.z; hi.y = s.z * F.w; hi.z = s.w * F.z; hi.w = s.w * F.w;
        __stcs(reinterpret_cast<float4*>(orow + OUT_W) + 0, lo);
        __stcs(reinterpret_cast<float4*>(orow + OUT_W) + 1, hi);
    }
}

extern "C" void kernel_launch(void* const* d_in, const int* in_sizes, int n_in,
                              void* d_out, int out_size) {
    const float* x       = (const float*)d_in[0];
    const float* filters = (const float*)d_in[1];
    float* out           = (float*)d_out;

    // total threads = B * C * H * W4 = 4*64*256*64 = 4,194,304
    const int total = B * C * H * W4;
    idwt2d_kernel<<<total / 256, 256>>>(x, filters, out);
}

// round 3
// speedup vs baseline: 1.3029x; 1.3029x over previous
#include <cuda_runtime.h>
#include <cstdint>

// IDWT_2D: x [B=4, 4*C=256, H=256, W=256] f32, filters [4,2,2] f32
// s[b,g,h,w] = sum_n x[b, n*64+g, h, w]
// y[b, g*4+j, 2h+a, 2w+c] = s[b,g,h,w] * f[j,a,c]
// Output: [4, 256, 512, 512] f32

static constexpr int B = 4;
static constexpr int C = 64;                 // groups
static constexpr int H = 256;
static constexpr int W = 256;
static constexpr int SUBBAND_STRIDE = C * H * W;      // offset between sub-bands n
static constexpr int OUT_W = 2 * W;                   // 512
static constexpr int OUT_CH_STRIDE = (2 * H) * OUT_W; // 512*512

// One warp handles one (b, g, h, half) = 128 consecutive input pixels.
// Thread k holds input pixels {2k, 2k+1} (s0) and {64+2k, 64+2k+1} (s1).
// Every STG.128 across the warp is then a contiguous 512B block (thread k at
// byte 16k) — full sectors, 4 wavefronts per instruction.
__global__ __launch_bounds__(256) void idwt2d_kernel(
    const float* __restrict__ x,
    const float* __restrict__ filters,
    float* __restrict__ out)
{
    unsigned seg = blockIdx.x * 8u + (threadIdx.x >> 5);  // global warp id
    int lane = threadIdx.x & 31;
    int half = seg & 1;                 // which half of the input row
    int h    = (seg >> 1) & (H - 1);
    int g    = (seg >> 9) & (C - 1);
    int b    = seg >> 15;

    // input row base for sub-band 0, this warp's half-row, this lane
    const float* xb = x + (((size_t)(b * 4 * C + g) * H + h) * W)
                        + half * 128 + 2 * lane;

    // gather + sum the 4 sub-bands (coalesced float2 loads: 8B/lane)
    float2 s0 = *reinterpret_cast<const float2*>(xb);
    float2 s1 = *reinterpret_cast<const float2*>(xb + 64);
    #pragma unroll
    for (int n = 1; n < 4; ++n) {
        float2 t0 = *reinterpret_cast<const float2*>(xb + n * SUBBAND_STRIDE);
        float2 t1 = *reinterpret_cast<const float2*>(xb + n * SUBBAND_STRIDE + 64);
        s0.x += t0.x; s0.y += t0.y;
        s1.x += t1.x; s1.y += t1.y;
    }

    // filters: [4,2,2] -> one float4 per j: {a0c0, a0c1, a1c0, a1c1}
    const float4* f4 = reinterpret_cast<const float4*>(filters);

    // output base: channel g*4, row 2h, column 256*half + 4*lane
    float* obase = out + ((size_t)(b * 4 * C + g * 4) * (2 * H) + 2 * h) * OUT_W
                       + half * 256 + 4 * lane;

    #pragma unroll
    for (int j = 0; j < 4; ++j) {
        float4 F = __ldg(f4 + j);
        float* orow = obase + (size_t)j * OUT_CH_STRIDE;

        float4 v;
        // a = 0, first 512B block (from s0: pixels 2k, 2k+1)
        v.x = s0.x * F.x; v.y = s0.x * F.y; v.z = s0.y * F.x; v.w = s0.y * F.y;
        reinterpret_cast<float4*>(orow)[0] = v;
        // a = 0, second 512B block (from s1: pixels 64+2k, 64+2k+1)
        v.x = s1.x * F.x; v.y = s1.x * F.y; v.z = s1.y * F.x; v.w = s1.y * F.y;
        reinterpret_cast<float4*>(orow + 128)[0] = v;
        // a = 1 row
        v.x = s0.x * F.z; v.y = s0.x * F.w; v.z = s0.y * F.z; v.w = s0.y * F.w;
        reinterpret_cast<float4*>(orow + OUT_W)[0] = v;
        v.x = s1.x * F.z; v.y = s1.x * F.w; v.z = s1.y * F.z; v.w = s1.y * F.w;
        reinterpret_cast<float4*>(orow + OUT_W + 128)[0] = v;
    }
}

extern "C" void kernel_launch(void* const* d_in, const int* in_sizes, int n_in,
                              void* d_out, int out_size) {
    const float* x       = (const float*)d_in[0];
    const float* filters = (const float*)d_in[1];
    float* out           = (float*)d_out;

    // total warps = B*C*H*2 = 131072 ; 8 warps/block -> 16384 blocks
    idwt2d_kernel<<<16384, 256>>>(x, filters, out);
}